// round 10
// baseline (speedup 1.0000x reference)
#include <cuda_runtime.h>
#include <cuda_fp16.h>
#include <cstdint>

// Problem constants
#define B_SZ   4096
#define F_SZ   100
#define H_SZ   128
#define H2_SZ  64
#define T_SZ   2

// Tiling: 2 independent 128-thread groups per CTA; each group: 64 rows x FG features
#define TB      64      // batch rows per CTA (shared by both groups)
#define FG      2       // features per GROUP
#define NSTEP   (3 * FG)
#define THREADS 256
#define GT      128     // threads per group
#define WB32    8192    // uint32 entries per packed 32KB fp16 weight matrix

// Fragment-packed fp16 weights: [layer][f][8192] uint32 (f16x2)
// entry e = ((ks*16 + nt)*32 + lane); regs at 2e, 2e+1
__device__ uint32_t g_wp[3][F_SZ][WB32];
// Collapsed head
__device__ float g_wv[F_SZ * T_SZ * H_SZ];
__device__ float g_c[F_SZ * T_SZ];

// ---------------- scalar helpers ----------------
__device__ __forceinline__ float elu_f(float v) {
    return v > 0.0f ? v : (__expf(v) - 1.0f);
}
__device__ __forceinline__ uint32_t pack2h(float v0, float v1) {
    uint32_t p;
    asm("cvt.rn.f16x2.f32 %0, %1, %2;" : "=r"(p) : "f"(v1), "f"(v0));
    return p;
}

// mma.sync m16n8k16 fp16 -> fp32 (baseline PTX, compiles under compute_103)
__device__ __forceinline__ void mma16816(float d[4], const uint32_t a[4],
                                         uint32_t b0, uint32_t b1) {
    asm("mma.sync.aligned.m16n8k16.row.col.f32.f16.f16.f32 "
        "{%0,%1,%2,%3}, {%4,%5,%6,%7}, {%8,%9}, {%0,%1,%2,%3};"
        : "+f"(d[0]), "+f"(d[1]), "+f"(d[2]), "+f"(d[3])
        : "r"(a[0]), "r"(a[1]), "r"(a[2]), "r"(a[3]), "r"(b0), "r"(b1));
}

// ---------------- cp.async ----------------
__device__ __forceinline__ void cp16(uint32_t saddr, const void* g) {
    asm volatile("cp.async.cg.shared.global [%0], [%1], 16;\n" :: "r"(saddr), "l"(g));
}
__device__ __forceinline__ void cp_commit() {
    asm volatile("cp.async.commit_group;\n" ::: "memory");
}
__device__ __forceinline__ void cp_wait0() {
    asm volatile("cp.async.wait_group 0;\n" ::: "memory");
}
__device__ __forceinline__ void cp_wait1() {
    asm volatile("cp.async.wait_group 1;\n" ::: "memory");
}
// copy one 32KB packed weight matrix with 128 threads (16 x 16B per thread)
__device__ __forceinline__ void issue_w(uint32_t sdst, const char* gsrc, int gt) {
#pragma unroll
    for (int i = 0; i < 16; i++) {
        int b = (gt + i * GT) * 16;
        cp16(sdst + b, gsrc + b);
    }
    cp_commit();
}

// ---------------- setup: pack weights, head collapse, zero out ----------------
__global__ void nam_setup(float* __restrict__ out, int n_out,
                          const float* __restrict__ W2, const float* __restrict__ W3,
                          const float* __restrict__ W4,
                          const float* __restrict__ Wh1, const float* __restrict__ bh1,
                          const float* __restrict__ Wh2, const float* __restrict__ bh2) {
    const int blk = blockIdx.x;
    const int tid = threadIdx.x;
    if (blk < 3 * F_SZ) {
        const int l = blk / F_SZ, f = blk % F_SZ;
        const float* W = (l == 0 ? W2 : (l == 1 ? W3 : W4)) + (long)f * H_SZ * H_SZ;
        uint32_t* hi = &g_wp[l][f][0];
        for (int e = tid; e < 4096; e += THREADS) {
            const int lane = e & 31;
            const int t = lane & 3, g = lane >> 2;
            const int nt = (e >> 5) & 15, ks = e >> 9;
            const int n = nt * 8 + g;
            const int k0 = ks * 16 + t * 2;
            float w00 = W[(k0)     * H_SZ + n];
            float w01 = W[(k0 + 1) * H_SZ + n];
            float w10 = W[(k0 + 8) * H_SZ + n];
            float w11 = W[(k0 + 9) * H_SZ + n];
            hi[2 * e]     = pack2h(w00, w01);
            hi[2 * e + 1] = pack2h(w10, w11);
        }
    } else if (blk < 3 * F_SZ + F_SZ * T_SZ) {
        const int ft = blk - 3 * F_SZ;
        __shared__ float s2[H2_SZ];
        if (tid < H2_SZ) s2[tid] = Wh2[ft * H2_SZ + tid];
        __syncthreads();
        if (tid < H_SZ) {
            const float* wp = Wh1 + ((long)ft * H_SZ + tid) * H2_SZ;
            float s = 0.0f;
#pragma unroll 8
            for (int m = 0; m < H2_SZ; m++) s += wp[m] * s2[m];
            g_wv[ft * H_SZ + tid] = s;
            if (tid == 0) {
                float cc = bh2[ft];
                const float* bp = bh1 + ft * H2_SZ;
                for (int m = 0; m < H2_SZ; m++) cc += bp[m] * s2[m];
                g_c[ft] = cc;
            }
        }
    } else {
        int i = (blk - (3 * F_SZ + F_SZ * T_SZ)) * THREADS + tid;
        if (i < n_out) out[i] = 0.0f;
    }
}

// ---------------- fused main kernel ----------------
// smem: [0,32K) g0 buf0, [32K,64K) g0 buf1, [64K,96K) g1 buf0, [96K,128K) g1 buf1
#define FS_OFF  131072
#define GF      1024     // floats of small area per group
#define SX_I    0        // 64
#define SW1_I   64       // 128
#define SB1_I   192      // 128
#define SBIAS_I 320      // 384 (b2|b3|b4)
#define SWV_I   704      // 256
#define SC_I    960      // 2
#define SMEM_BYTES (FS_OFF + 2 * GF * 4)

#define GBAR() asm volatile("bar.sync %0, 128;" :: "r"(gid + 1) : "memory")

__global__ void __launch_bounds__(THREADS, 1)
nam_main(const float* __restrict__ x, const int* __restrict__ a,
         const float* __restrict__ W1, const float* __restrict__ b1,
         const float* __restrict__ b2, const float* __restrict__ b3,
         const float* __restrict__ b4, float* __restrict__ out) {
    extern __shared__ char smem[];

    const int tid = threadIdx.x;
    const int gid = tid >> 7;        // group 0/1
    const int gt  = tid & 127;       // thread within group
    const int w4 = gt >> 5, lane = gt & 31;
    const int t = lane & 3, g = lane >> 2;
    const int t2 = t * 2;
    const int lr0 = 16 * w4 + g;     // local row (acc c0/c1), 0..63
    const int lr1 = lr0 + 8;
    const int b0 = blockIdx.x * TB;
    const int fbase = blockIdx.y * (2 * FG) + gid * FG;
    const int grow0 = b0 + lr0, grow1 = b0 + lr1;

    float* fs  = (float*)(smem + FS_OFF) + gid * GF;
    float* sx    = fs + SX_I;
    float* sw1   = fs + SW1_I;
    float* sb1   = fs + SB1_I;
    float* sbias = fs + SBIAS_I;
    float* swv   = fs + SWV_I;
    float* sc    = fs + SC_I;

    const uint32_t smem_u32 = (uint32_t)__cvta_generic_to_shared(smem);
    const uint32_t wgbase = smem_u32 + (uint32_t)gid * 65536u;
    const char* const wgen = smem + gid * 65536;

    const int t0 = a[grow0], t1 = a[grow1];
    const int t0w = t0 * H_SZ, t1w = t1 * H_SZ;

    float acc[16][4];
    uint32_t Ah[8][4];
    float bbs[16][4];
#pragma unroll
    for (int nt = 0; nt < 16; nt++)
#pragma unroll
        for (int j = 0; j < 4; j++) bbs[nt][j] = 0.0f;
    float yacc0 = 0.0f, yacc1 = 0.0f;

    // prologue: steps 0 and 1 (feature fbase, layers W2 and W3)
    issue_w(wgbase,          (const char*)&g_wp[0][fbase][0], gt);
    issue_w(wgbase + 32768u, (const char*)&g_wp[1][fbase][0], gt);

    for (int ff = 0; ff < FG; ff++) {
        const int f = fbase + ff;
        GBAR();   // prev feature consumers done with small buffers
        if (gt < TB) sx[gt] = x[(long)(b0 + gt) * F_SZ + f];
        sw1[gt]         = W1[f * H_SZ + gt];
        sb1[gt]         = b1[f * H_SZ + gt];
        sbias[gt]       = b2[f * H_SZ + gt];
        sbias[128 + gt] = b3[f * H_SZ + gt];
        sbias[256 + gt] = b4[f * H_SZ + gt];
        swv[gt]       = g_wv[f * 256 + gt];
        swv[128 + gt] = g_wv[f * 256 + 128 + gt];
        if (gt < 2) sc[gt] = g_c[f * 2 + gt];
        GBAR();

        // ---- layer 1: build fp16 A-fragments directly ----
        {
            const float xv0 = sx[lr0], xv1 = sx[lr1];
#pragma unroll
            for (int kk = 0; kk < 8; kk++) {
                const int cA = 16 * kk + t2, cB = cA + 8;
                float2 wA = *(const float2*)&sw1[cA];
                float2 bA = *(const float2*)&sb1[cA];
                float2 wB = *(const float2*)&sw1[cB];
                float2 bB = *(const float2*)&sb1[cB];
                Ah[kk][0] = pack2h(elu_f(xv0 * wA.x + bA.x),
                                   elu_f(xv0 * wA.y + bA.y));
                Ah[kk][1] = pack2h(elu_f(xv1 * wA.x + bA.x),
                                   elu_f(xv1 * wA.y + bA.y));
                Ah[kk][2] = pack2h(elu_f(xv0 * wB.x + bB.x),
                                   elu_f(xv0 * wB.y + bB.y));
                Ah[kk][3] = pack2h(elu_f(xv1 * wB.x + bB.x),
                                   elu_f(xv1 * wB.y + bB.y));
            }
        }

#pragma unroll 1
        for (int l = 0; l < 3; l++) {
            const int step = ff * 3 + l;
            if (step == NSTEP - 1) cp_wait0(); else cp_wait1();
            GBAR();   // this step's weight buffer ready & visible to group

            const uint32_t* Wh =
                (const uint32_t*)(wgen + (step & 1) * 32768);

            // ---- single-pass fp16 GEMM ----
#pragma unroll
            for (int nt = 0; nt < 16; nt++) {
                acc[nt][0] = 0.f; acc[nt][1] = 0.f;
                acc[nt][2] = 0.f; acc[nt][3] = 0.f;
            }
#pragma unroll
            for (int ks = 0; ks < 8; ks++) {
                const uint32_t* bh = Wh + ks * 1024 + lane * 2;
#pragma unroll
                for (int nt = 0; nt < 16; nt++) {
                    uint2 wh = *(const uint2*)(bh + nt * 64);
                    mma16816(acc[nt], Ah[ks], wh.x, wh.y);
                }
            }

            GBAR();   // all group threads done reading this weight buffer

            // prefetch step+2 into the buffer just released
            const int s2 = step + 2;
            if (s2 < NSTEP)
                issue_w(wgbase + (uint32_t)(step & 1) * 32768u,
                        (const char*)&g_wp[s2 % 3][fbase + s2 / 3][0], gt);

            if (l < 2) {
                // ---- epilogue: bias + ELU + fp16 pack -> next A frags ----
                const float* sb = sbias + l * 128;
#pragma unroll
                for (int kk = 0; kk < 8; kk++) {
                    const int nt0 = 2 * kk, nt1 = 2 * kk + 1;
                    float2 bA = *(const float2*)&sb[8 * nt0 + t2];
                    float2 bB = *(const float2*)&sb[8 * nt1 + t2];
                    Ah[kk][0] = pack2h(elu_f(acc[nt0][0] + bA.x),
                                       elu_f(acc[nt0][1] + bA.y));
                    Ah[kk][1] = pack2h(elu_f(acc[nt0][2] + bA.x),
                                       elu_f(acc[nt0][3] + bA.y));
                    Ah[kk][2] = pack2h(elu_f(acc[nt1][0] + bB.x),
                                       elu_f(acc[nt1][1] + bB.y));
                    Ah[kk][3] = pack2h(elu_f(acc[nt1][2] + bB.x),
                                       elu_f(acc[nt1][3] + bB.y));
                }
            } else {
                // ---- layer-4 epilogue: bb accumulate + collapsed head ----
                const float* sb4 = sbias + 256;
                float y0 = 0.0f, y1 = 0.0f;
#pragma unroll
                for (int nt = 0; nt < 16; nt++) {
                    float2 b4v = *(const float2*)&sb4[8 * nt + t2];
                    float bb0 = acc[nt][0] + b4v.x;
                    float bb1 = acc[nt][1] + b4v.y;
                    float bb2 = acc[nt][2] + b4v.x;
                    float bb3 = acc[nt][3] + b4v.y;
                    bbs[nt][0] += bb0; bbs[nt][1] += bb1;
                    bbs[nt][2] += bb2; bbs[nt][3] += bb3;
                    float2 wv0 = *(const float2*)&swv[t0w + 8 * nt + t2];
                    float2 wv1 = *(const float2*)&swv[t1w + 8 * nt + t2];
                    y0 += bb0 * wv0.x + bb1 * wv0.y;
                    y1 += bb2 * wv1.x + bb3 * wv1.y;
                }
                if (t == 0) { y0 += sc[t0]; y1 += sc[t1]; }
                yacc0 += y0; yacc1 += y1;
            }
        }
    }

    // ---- finale: atomics into output ----
#pragma unroll
    for (int nt = 0; nt < 16; nt++) {
        const int col = 8 * nt + t2;
        atomicAdd(&out[(long)grow0 * H_SZ + col],     bbs[nt][0]);
        atomicAdd(&out[(long)grow0 * H_SZ + col + 1], bbs[nt][1]);
        atomicAdd(&out[(long)grow1 * H_SZ + col],     bbs[nt][2]);
        atomicAdd(&out[(long)grow1 * H_SZ + col + 1], bbs[nt][3]);
    }
    yacc0 += __shfl_xor_sync(0xffffffffu, yacc0, 1);
    yacc0 += __shfl_xor_sync(0xffffffffu, yacc0, 2);
    yacc1 += __shfl_xor_sync(0xffffffffu, yacc1, 1);
    yacc1 += __shfl_xor_sync(0xffffffffu, yacc1, 2);
    if (t == 0) {
        atomicAdd(&out[B_SZ * H_SZ + grow0], yacc0);
        atomicAdd(&out[B_SZ * H_SZ + grow1], yacc1);
    }
}

// ---------------- launch ----------------
extern "C" void kernel_launch(void* const* d_in, const int* in_sizes, int n_in,
                              void* d_out, int out_size) {
    const float* x   = (const float*)d_in[0];
    const int*   a   = (const int*)d_in[1];
    const float* W1  = (const float*)d_in[2];
    const float* b1  = (const float*)d_in[3];
    const float* W2  = (const float*)d_in[4];
    const float* b2  = (const float*)d_in[5];
    const float* W3  = (const float*)d_in[6];
    const float* b3  = (const float*)d_in[7];
    const float* W4  = (const float*)d_in[8];
    const float* b4  = (const float*)d_in[9];
    const float* Wh1 = (const float*)d_in[10];
    const float* bh1 = (const float*)d_in[11];
    const float* Wh2 = (const float*)d_in[12];
    const float* bh2 = (const float*)d_in[13];
    float* out = (float*)d_out;

    cudaFuncSetAttribute(nam_main, cudaFuncAttributeMaxDynamicSharedMemorySize,
                         SMEM_BYTES);

    const int zero_blocks = (out_size + THREADS - 1) / THREADS;
    nam_setup<<<3 * F_SZ + F_SZ * T_SZ + zero_blocks, THREADS>>>(
        out, out_size, W2, W3, W4, Wh1, bh1, Wh2, bh2);

    dim3 grid(B_SZ / TB, F_SZ / (2 * FG));
    nam_main<<<grid, THREADS, SMEM_BYTES>>>(x, a, W1, b1, b2, b3, b4, out);
}

// round 11
// speedup vs baseline: 1.2410x; 1.2410x over previous
#include <cuda_runtime.h>
#include <cuda_fp16.h>
#include <cstdint>

// Problem constants
#define B_SZ   4096
#define F_SZ   100
#define H_SZ   128
#define H2_SZ  64
#define T_SZ   2

// Tiling: 2 independent 128-thread groups per CTA; each group: 64 rows x FG features
#define TB      64      // batch rows per CTA (shared by both groups)
#define FG      2       // features per GROUP
#define NSTEP   (3 * FG)
#define THREADS 256
#define GT      128     // threads per group
#define WB32    8192    // uint32 entries per packed 32KB fp16 weight matrix

// Fragment-packed fp16 weights: [layer][f][2][8192] uint32 (hi, lo residual)
// entry e = ((ks*16 + nt)*32 + lane); regs at 2e, 2e+1
__device__ uint32_t g_wp[3][F_SZ][2][WB32];
// Collapsed head
__device__ float g_wv[F_SZ * T_SZ * H_SZ];
__device__ float g_c[F_SZ * T_SZ];

// ---------------- scalar helpers ----------------
__device__ __forceinline__ float elu_f(float v) {
    return v > 0.0f ? v : (__expf(v) - 1.0f);
}
// pack two fp32 into f16x2 (low half = v0), return fp32 residuals
__device__ __forceinline__ uint32_t pack_split(float v0, float v1, float& r0, float& r1) {
    uint32_t p;
    asm("cvt.rn.f16x2.f32 %0, %1, %2;" : "=r"(p) : "f"(v1), "f"(v0));
    float f0, f1;
    asm("{.reg .b16 l,h; mov.b32 {l,h}, %2; cvt.f32.f16 %0, l; cvt.f32.f16 %1, h;}"
        : "=f"(f0), "=f"(f1) : "r"(p));
    r0 = v0 - f0; r1 = v1 - f1;
    return p;
}
__device__ __forceinline__ uint32_t pack2h(float v0, float v1) {
    uint32_t p;
    asm("cvt.rn.f16x2.f32 %0, %1, %2;" : "=r"(p) : "f"(v1), "f"(v0));
    return p;
}

// mma.sync m16n8k16 fp16 -> fp32
__device__ __forceinline__ void mma16816(float d[4], const uint32_t a[4],
                                         uint32_t b0, uint32_t b1) {
    asm("mma.sync.aligned.m16n8k16.row.col.f32.f16.f16.f32 "
        "{%0,%1,%2,%3}, {%4,%5,%6,%7}, {%8,%9}, {%0,%1,%2,%3};"
        : "+f"(d[0]), "+f"(d[1]), "+f"(d[2]), "+f"(d[3])
        : "r"(a[0]), "r"(a[1]), "r"(a[2]), "r"(a[3]), "r"(b0), "r"(b1));
}

// ---------------- cp.async ----------------
__device__ __forceinline__ void cp16(uint32_t saddr, const void* g) {
    asm volatile("cp.async.cg.shared.global [%0], [%1], 16;\n" :: "r"(saddr), "l"(g));
}
__device__ __forceinline__ void cp_commit() {
    asm volatile("cp.async.commit_group;\n" ::: "memory");
}
__device__ __forceinline__ void cp_wait0() {
    asm volatile("cp.async.wait_group 0;\n" ::: "memory");
}
__device__ __forceinline__ void cp_wait1() {
    asm volatile("cp.async.wait_group 1;\n" ::: "memory");
}
// copy one 64KB packed weight block (hi 32KB | lo 32KB) with 128 threads
__device__ __forceinline__ void issue_w(uint32_t sdst, const char* gsrc, int gt) {
#pragma unroll
    for (int i = 0; i < 32; i++) {
        int b = (gt + i * GT) * 16;
        cp16(sdst + b, gsrc + b);
    }
    cp_commit();
}

// ---------------- setup: pack weights, head collapse, zero out ----------------
__global__ void nam_setup(float* __restrict__ out, int n_out,
                          const float* __restrict__ W2, const float* __restrict__ W3,
                          const float* __restrict__ W4,
                          const float* __restrict__ Wh1, const float* __restrict__ bh1,
                          const float* __restrict__ Wh2, const float* __restrict__ bh2) {
    const int blk = blockIdx.x;
    const int tid = threadIdx.x;
    if (blk < 3 * F_SZ) {
        const int l = blk / F_SZ, f = blk % F_SZ;
        const float* W = (l == 0 ? W2 : (l == 1 ? W3 : W4)) + (long)f * H_SZ * H_SZ;
        uint32_t* hi = &g_wp[l][f][0][0];
        uint32_t* lo = &g_wp[l][f][1][0];
        for (int e = tid; e < 4096; e += THREADS) {
            const int lane = e & 31;
            const int t = lane & 3, g = lane >> 2;
            const int nt = (e >> 5) & 15, ks = e >> 9;
            const int n = nt * 8 + g;
            const int k0 = ks * 16 + t * 2;
            float w00 = W[(k0)     * H_SZ + n];
            float w01 = W[(k0 + 1) * H_SZ + n];
            float w10 = W[(k0 + 8) * H_SZ + n];
            float w11 = W[(k0 + 9) * H_SZ + n];
            float r00, r01, r10, r11;
            hi[2 * e]     = pack_split(w00, w01, r00, r01);
            hi[2 * e + 1] = pack_split(w10, w11, r10, r11);
            lo[2 * e]     = pack2h(r00, r01);
            lo[2 * e + 1] = pack2h(r10, r11);
        }
    } else if (blk < 3 * F_SZ + F_SZ * T_SZ) {
        const int ft = blk - 3 * F_SZ;
        __shared__ float s2[H2_SZ];
        if (tid < H2_SZ) s2[tid] = Wh2[ft * H2_SZ + tid];
        __syncthreads();
        if (tid < H_SZ) {
            const float* wp = Wh1 + ((long)ft * H_SZ + tid) * H2_SZ;
            float s = 0.0f;
#pragma unroll 8
            for (int m = 0; m < H2_SZ; m++) s += wp[m] * s2[m];
            g_wv[ft * H_SZ + tid] = s;
            if (tid == 0) {
                float cc = bh2[ft];
                const float* bp = bh1 + ft * H2_SZ;
                for (int m = 0; m < H2_SZ; m++) cc += bp[m] * s2[m];
                g_c[ft] = cc;
            }
        }
    } else {
        int i = (blk - (3 * F_SZ + F_SZ * T_SZ)) * THREADS + tid;
        if (i < n_out) out[i] = 0.0f;
    }
}

// ---------------- fused main kernel ----------------
// smem: per group 3 x 64KB? No: 3 buffers x 64KB won't fit. Each step's block is
// 64KB (hi+lo). Triple buffering needs 3 x 64KB x 2 groups = 384KB -> too big.
// Instead: 3 buffers of 32KB per half... Use hi+lo as ONE 64KB unit with
// 1.5-deep? Compromise: keep 2 x 64KB double buffer per group (R9 scheme needs
// 2 x 32KB only because weights were single fp16; 2-pass needs hi+lo = 64KB).
// 2 groups x 2 bufs x 64KB = 256KB > 227KB. So: groups SHARE features
// (same fbase for both groups? No - they process different features).
//
// Resolution: R9 actually used hi-only 32KB... no, R9 was 2-pass with hi+lo
// packed... R9 used g_wp[3][F][WB32] single fp16 = R10's layout. R8/R9 2-pass
// used Ah/Al x same Wh (A split, W single fp16). THAT is the 299.5 config:
// weights single fp16 (32KB), A split in registers. Keep exactly that, add
// triple buffering: 3 x 32KB x 2 groups = 192KB. OK.
#define FS_OFF  196608
#define GF      1024     // floats of small area per group
#define SX_I    0        // 64
#define SW1_I   64       // 128
#define SB1_I   192      // 128
#define SBIAS_I 320      // 384 (b2|b3|b4)
#define SWV_I   704      // 256
#define SC_I    960      // 2
#define SMEM_BYTES (FS_OFF + 2 * GF * 4)

#define GBAR() asm volatile("bar.sync %0, 128;" :: "r"(gid + 1) : "memory")

__global__ void __launch_bounds__(THREADS, 1)
nam_main(const float* __restrict__ x, const int* __restrict__ a,
         const float* __restrict__ W1, const float* __restrict__ b1,
         const float* __restrict__ b2, const float* __restrict__ b3,
         const float* __restrict__ b4, float* __restrict__ out) {
    extern __shared__ char smem[];

    const int tid = threadIdx.x;
    const int gid = tid >> 7;        // group 0/1
    const int gt  = tid & 127;       // thread within group
    const int w4 = gt >> 5, lane = gt & 31;
    const int t = lane & 3, g = lane >> 2;
    const int t2 = t * 2;
    const int lr0 = 16 * w4 + g;     // local row (acc c0/c1), 0..63
    const int lr1 = lr0 + 8;
    const int b0 = blockIdx.x * TB;
    const int fbase = blockIdx.y * (2 * FG) + gid * FG;
    const int grow0 = b0 + lr0, grow1 = b0 + lr1;

    float* fs  = (float*)(smem + FS_OFF) + gid * GF;
    float* sx    = fs + SX_I;
    float* sw1   = fs + SW1_I;
    float* sb1   = fs + SB1_I;
    float* sbias = fs + SBIAS_I;
    float* swv   = fs + SWV_I;
    float* sc    = fs + SC_I;

    const uint32_t smem_u32 = (uint32_t)__cvta_generic_to_shared(smem);
    const uint32_t wgbase = smem_u32 + (uint32_t)gid * 98304u;   // 3 x 32KB
    const char* const wgen = smem + gid * 98304;

    const int t0 = a[grow0], t1 = a[grow1];
    const int t0w = t0 * H_SZ, t1w = t1 * H_SZ;

    float acc[16][4];
    uint32_t Ah[8][4], Al[8][4];
    float bbs[16][4];
#pragma unroll
    for (int nt = 0; nt < 16; nt++)
#pragma unroll
        for (int j = 0; j < 4; j++) bbs[nt][j] = 0.0f;
    float yacc0 = 0.0f, yacc1 = 0.0f;

    // prologue: steps 0 and 1 into buffers 0 and 1 (single-fp16 weights, hi only)
    // copy 32KB with 128 threads: 16 x 16B each
    {
        const char* g0 = (const char*)&g_wp[0][fbase][0][0];
        const char* g1 = (const char*)&g_wp[1][fbase][0][0];
#pragma unroll
        for (int i = 0; i < 16; i++) {
            int b = (gt + i * GT) * 16;
            cp16(wgbase + b, g0 + b);
        }
        cp_commit();
#pragma unroll
        for (int i = 0; i < 16; i++) {
            int b = (gt + i * GT) * 16;
            cp16(wgbase + 32768u + b, g1 + b);
        }
        cp_commit();
    }

    for (int ff = 0; ff < FG; ff++) {
        const int f = fbase + ff;
        GBAR();   // prev feature consumers done with small buffers
        if (gt < TB) sx[gt] = x[(long)(b0 + gt) * F_SZ + f];
        sw1[gt]         = W1[f * H_SZ + gt];
        sb1[gt]         = b1[f * H_SZ + gt];
        sbias[gt]       = b2[f * H_SZ + gt];
        sbias[128 + gt] = b3[f * H_SZ + gt];
        sbias[256 + gt] = b4[f * H_SZ + gt];
        swv[gt]       = g_wv[f * 256 + gt];
        swv[128 + gt] = g_wv[f * 256 + 128 + gt];
        if (gt < 2) sc[gt] = g_c[f * 2 + gt];
        GBAR();

        // ---- layer 1: build A-fragments directly (hi/lo fp16 split) ----
        {
            const float xv0 = sx[lr0], xv1 = sx[lr1];
#pragma unroll
            for (int kk = 0; kk < 8; kk++) {
                const int cA = 16 * kk + t2, cB = cA + 8;
                float2 wA = *(const float2*)&sw1[cA];
                float2 bA = *(const float2*)&sb1[cA];
                float2 wB = *(const float2*)&sw1[cB];
                float2 bB = *(const float2*)&sb1[cB];
                float r0, r1;
                float v0 = elu_f(xv0 * wA.x + bA.x);
                float v1 = elu_f(xv0 * wA.y + bA.y);
                Ah[kk][0] = pack_split(v0, v1, r0, r1); Al[kk][0] = pack2h(r0, r1);
                v0 = elu_f(xv1 * wA.x + bA.x);
                v1 = elu_f(xv1 * wA.y + bA.y);
                Ah[kk][1] = pack_split(v0, v1, r0, r1); Al[kk][1] = pack2h(r0, r1);
                v0 = elu_f(xv0 * wB.x + bB.x);
                v1 = elu_f(xv0 * wB.y + bB.y);
                Ah[kk][2] = pack_split(v0, v1, r0, r1); Al[kk][2] = pack2h(r0, r1);
                v0 = elu_f(xv1 * wB.x + bB.x);
                v1 = elu_f(xv1 * wB.y + bB.y);
                Ah[kk][3] = pack_split(v0, v1, r0, r1); Al[kk][3] = pack2h(r0, r1);
            }
        }

#pragma unroll 1
        for (int l = 0; l < 3; l++) {
            const int step = ff * 3 + l;
            if (step == NSTEP - 1) cp_wait0(); else cp_wait1();
            GBAR();   // buffer step%3 ready & all warps past step-1 GEMM

            // prefetch step+2 into buffer (step+2)%3 (last read at step-1)
            const int s2 = step + 2;
            if (s2 < NSTEP) {
                const char* nx = (const char*)&g_wp[s2 % 3][fbase + s2 / 3][0][0];
                const uint32_t dst = wgbase + (uint32_t)(s2 % 3) * 32768u;
#pragma unroll
                for (int i = 0; i < 16; i++) {
                    int b = (gt + i * GT) * 16;
                    cp16(dst + b, nx + b);
                }
                cp_commit();
            }

            const uint32_t* Wh =
                (const uint32_t*)(wgen + (step % 3) * 32768) + lane * 2;

            // ---- 2-pass split GEMM, register-pipelined B fragments ----
#pragma unroll
            for (int nt = 0; nt < 16; nt++) {
                acc[nt][0] = 0.f; acc[nt][1] = 0.f;
                acc[nt][2] = 0.f; acc[nt][3] = 0.f;
            }
            {
                uint2 wh = *(const uint2*)(Wh);
#pragma unroll
                for (int idx = 0; idx < 128; idx++) {
                    const int ks = idx >> 4, nt = idx & 15;
                    uint2 wh_n;
                    if (idx < 127) {
                        const int idx1 = idx + 1;
                        const int off = (idx1 >> 4) * 1024 + (idx1 & 15) * 64;
                        wh_n = *(const uint2*)(Wh + off);
                    }
                    mma16816(acc[nt], Ah[ks], wh.x, wh.y);
                    mma16816(acc[nt], Al[ks], wh.x, wh.y);
                    wh = wh_n;
                }
            }

            if (l < 2) {
                // ---- epilogue: bias + ELU + split -> next layer's A frags ----
                const float* sb = sbias + l * 128;
#pragma unroll
                for (int kk = 0; kk < 8; kk++) {
                    const int nt0 = 2 * kk, nt1 = 2 * kk + 1;
                    float2 bA = *(const float2*)&sb[8 * nt0 + t2];
                    float2 bB = *(const float2*)&sb[8 * nt1 + t2];
                    float r0, r1;
                    float v0 = elu_f(acc[nt0][0] + bA.x);
                    float v1 = elu_f(acc[nt0][1] + bA.y);
                    Ah[kk][0] = pack_split(v0, v1, r0, r1); Al[kk][0] = pack2h(r0, r1);
                    v0 = elu_f(acc[nt0][2] + bA.x);
                    v1 = elu_f(acc[nt0][3] + bA.y);
                    Ah[kk][1] = pack_split(v0, v1, r0, r1); Al[kk][1] = pack2h(r0, r1);
                    v0 = elu_f(acc[nt1][0] + bB.x);
                    v1 = elu_f(acc[nt1][1] + bB.y);
                    Ah[kk][2] = pack_split(v0, v1, r0, r1); Al[kk][2] = pack2h(r0, r1);
                    v0 = elu_f(acc[nt1][2] + bB.x);
                    v1 = elu_f(acc[nt1][3] + bB.y);
                    Ah[kk][3] = pack_split(v0, v1, r0, r1); Al[kk][3] = pack2h(r0, r1);
                }
            } else {
                // ---- layer-4 epilogue: bb accumulate + collapsed head ----
                const float* sb4 = sbias + 256;
                float y0 = 0.0f, y1 = 0.0f;
#pragma unroll
                for (int nt = 0; nt < 16; nt++) {
                    float2 b4v = *(const float2*)&sb4[8 * nt + t2];
                    float bb0 = acc[nt][0] + b4v.x;
                    float bb1 = acc[nt][1] + b4v.y;
                    float bb2 = acc[nt][2] + b4v.x;
                    float bb3 = acc[nt][3] + b4v.y;
                    bbs[nt][0] += bb0; bbs[nt][1] += bb1;
                    bbs[nt][2] += bb2; bbs[nt][3] += bb3;
                    float2 wv0 = *(const float2*)&swv[t0w + 8 * nt + t2];
                    float2 wv1 = *(const float2*)&swv[t1w + 8 * nt + t2];
                    y0 += bb0 * wv0.x + bb1 * wv0.y;
                    y1 += bb2 * wv1.x + bb3 * wv1.y;
                }
                if (t == 0) { y0 += sc[t0]; y1 += sc[t1]; }
                yacc0 += y0; yacc1 += y1;
            }
        }
    }

    // ---- finale: atomics into output ----
#pragma unroll
    for (int nt = 0; nt < 16; nt++) {
        const int col = 8 * nt + t2;
        atomicAdd(&out[(long)grow0 * H_SZ + col],     bbs[nt][0]);
        atomicAdd(&out[(long)grow0 * H_SZ + col + 1], bbs[nt][1]);
        atomicAdd(&out[(long)grow1 * H_SZ + col],     bbs[nt][2]);
        atomicAdd(&out[(long)grow1 * H_SZ + col + 1], bbs[nt][3]);
    }
    yacc0 += __shfl_xor_sync(0xffffffffu, yacc0, 1);
    yacc0 += __shfl_xor_sync(0xffffffffu, yacc0, 2);
    yacc1 += __shfl_xor_sync(0xffffffffu, yacc1, 1);
    yacc1 += __shfl_xor_sync(0xffffffffu, yacc1, 2);
    if (t == 0) {
        atomicAdd(&out[B_SZ * H_SZ + grow0], yacc0);
        atomicAdd(&out[B_SZ * H_SZ + grow1], yacc1);
    }
}

// ---------------- launch ----------------
extern "C" void kernel_launch(void* const* d_in, const int* in_sizes, int n_in,
                              void* d_out, int out_size) {
    const float* x   = (const float*)d_in[0];
    const int*   a   = (const int*)d_in[1];
    const float* W1  = (const float*)d_in[2];
    const float* b1  = (const float*)d_in[3];
    const float* W2  = (const float*)d_in[4];
    const float* b2  = (const float*)d_in[5];
    const float* W3  = (const float*)d_in[6];
    const float* b3  = (const float*)d_in[7];
    const float* W4  = (const float*)d_in[8];
    const float* b4  = (const float*)d_in[9];
    const float* Wh1 = (const float*)d_in[10];
    const float* bh1 = (const float*)d_in[11];
    const float* Wh2 = (const float*)d_in[12];
    const float* bh2 = (const float*)d_in[13];
    float* out = (float*)d_out;

    cudaFuncSetAttribute(nam_main, cudaFuncAttributeMaxDynamicSharedMemorySize,
                         SMEM_BYTES);

    const int zero_blocks = (out_size + THREADS - 1) / THREADS;
    nam_setup<<<3 * F_SZ + F_SZ * T_SZ + zero_blocks, THREADS>>>(
        out, out_size, W2, W3, W4, Wh1, bh1, Wh2, bh2);

    dim3 grid(B_SZ / TB, F_SZ / (2 * FG));
    nam_main<<<grid, THREADS, SMEM_BYTES>>>(x, a, W1, b1, b2, b3, b4, out);
}

// round 12
// speedup vs baseline: 1.5786x; 1.2720x over previous
#include <cuda_runtime.h>
#include <cuda_fp16.h>
#include <cstdint>

// Problem constants
#define B_SZ   4096
#define F_SZ   100
#define H_SZ   128
#define H2_SZ  64
#define T_SZ   2

// Tiling: 2 independent 128-thread groups per CTA; each group: 64 rows x FG features
#define TB      64      // batch rows per CTA (shared by both groups)
#define FG      2       // features per GROUP
#define NSTEP   (3 * FG)
#define THREADS 256
#define GT      128     // threads per group
#define WB32    8192    // uint32 entries per packed 32KB fp16 weight matrix

// Fragment-PAIR-packed fp16 weights: [layer][f][8192] uint32 (f16x2)
// For (ks, nt, lane): offset = ks*1024 + (nt>>1)*128 + lane*4 + (nt&1)*2
// so fragments for nt and nt+1 share one 16B chunk -> LDS.128 feeds 2 HMMAs.
__device__ uint32_t g_wp[3][F_SZ][WB32];
// Collapsed head
__device__ float g_wv[F_SZ * T_SZ * H_SZ];
__device__ float g_c[F_SZ * T_SZ];

// ---------------- scalar helpers ----------------
__device__ __forceinline__ float elu_f(float v) {
    return v > 0.0f ? v : (__expf(v) - 1.0f);
}
__device__ __forceinline__ uint32_t pack2h(float v0, float v1) {
    uint32_t p;
    asm("cvt.rn.f16x2.f32 %0, %1, %2;" : "=r"(p) : "f"(v1), "f"(v0));
    return p;
}

// mma.sync m16n8k16 fp16 -> fp32
__device__ __forceinline__ void mma16816(float d[4], const uint32_t a[4],
                                         uint32_t b0, uint32_t b1) {
    asm("mma.sync.aligned.m16n8k16.row.col.f32.f16.f16.f32 "
        "{%0,%1,%2,%3}, {%4,%5,%6,%7}, {%8,%9}, {%0,%1,%2,%3};"
        : "+f"(d[0]), "+f"(d[1]), "+f"(d[2]), "+f"(d[3])
        : "r"(a[0]), "r"(a[1]), "r"(a[2]), "r"(a[3]), "r"(b0), "r"(b1));
}

// ---------------- cp.async ----------------
__device__ __forceinline__ void cp16(uint32_t saddr, const void* g) {
    asm volatile("cp.async.cg.shared.global [%0], [%1], 16;\n" :: "r"(saddr), "l"(g));
}
__device__ __forceinline__ void cp_commit() {
    asm volatile("cp.async.commit_group;\n" ::: "memory");
}
__device__ __forceinline__ void cp_wait0() {
    asm volatile("cp.async.wait_group 0;\n" ::: "memory");
}
__device__ __forceinline__ void cp_wait1() {
    asm volatile("cp.async.wait_group 1;\n" ::: "memory");
}

// ---------------- setup: pack weights, head collapse, zero out ----------------
__global__ void nam_setup(float* __restrict__ out, int n_out,
                          const float* __restrict__ W2, const float* __restrict__ W3,
                          const float* __restrict__ W4,
                          const float* __restrict__ Wh1, const float* __restrict__ bh1,
                          const float* __restrict__ Wh2, const float* __restrict__ bh2) {
    const int blk = blockIdx.x;
    const int tid = threadIdx.x;
    if (blk < 3 * F_SZ) {
        const int l = blk / F_SZ, f = blk % F_SZ;
        const float* W = (l == 0 ? W2 : (l == 1 ? W3 : W4)) + (long)f * H_SZ * H_SZ;
        uint32_t* hi = &g_wp[l][f][0];
        for (int e = tid; e < 4096; e += THREADS) {
            const int lane = e & 31;
            const int t = lane & 3, g = lane >> 2;
            const int nt = (e >> 5) & 15, ks = e >> 9;
            const int n = nt * 8 + g;
            const int k0 = ks * 16 + t * 2;
            float w00 = W[(k0)     * H_SZ + n];
            float w01 = W[(k0 + 1) * H_SZ + n];
            float w10 = W[(k0 + 8) * H_SZ + n];
            float w11 = W[(k0 + 9) * H_SZ + n];
            // paired layout: nt pairs share a 16B chunk
            const int base = ks * 1024 + (nt >> 1) * 128 + lane * 4 + (nt & 1) * 2;
            hi[base]     = pack2h(w00, w01);
            hi[base + 1] = pack2h(w10, w11);
        }
    } else if (blk < 3 * F_SZ + F_SZ * T_SZ) {
        const int ft = blk - 3 * F_SZ;
        __shared__ float s2[H2_SZ];
        if (tid < H2_SZ) s2[tid] = Wh2[ft * H2_SZ + tid];
        __syncthreads();
        if (tid < H_SZ) {
            const float* wp = Wh1 + ((long)ft * H_SZ + tid) * H2_SZ;
            float s = 0.0f;
#pragma unroll 8
            for (int m = 0; m < H2_SZ; m++) s += wp[m] * s2[m];
            g_wv[ft * H_SZ + tid] = s;
            if (tid == 0) {
                float cc = bh2[ft];
                const float* bp = bh1 + ft * H2_SZ;
                for (int m = 0; m < H2_SZ; m++) cc += bp[m] * s2[m];
                g_c[ft] = cc;
            }
        }
    } else {
        int i = (blk - (3 * F_SZ + F_SZ * T_SZ)) * THREADS + tid;
        if (i < n_out) out[i] = 0.0f;
    }
}

// ---------------- fused main kernel ----------------
// smem: per group 3 x 32KB weight ring; 2 groups = 192KB; + 2 x 4KB small areas
#define FS_OFF  196608
#define GF      1024     // floats of small area per group
#define SX_I    0        // 64
#define SW1_I   64       // 128
#define SB1_I   192      // 128
#define SBIAS_I 320      // 384 (b2|b3|b4)
#define SWV_I   704      // 256
#define SC_I    960      // 2
#define SMEM_BYTES (FS_OFF + 2 * GF * 4)

#define GBAR() asm volatile("bar.sync %0, 128;" :: "r"(gid + 1) : "memory")

__global__ void __launch_bounds__(THREADS, 1)
nam_main(const float* __restrict__ x, const int* __restrict__ a,
         const float* __restrict__ W1, const float* __restrict__ b1,
         const float* __restrict__ b2, const float* __restrict__ b3,
         const float* __restrict__ b4, float* __restrict__ out) {
    extern __shared__ char smem[];

    const int tid = threadIdx.x;
    const int gid = tid >> 7;        // group 0/1
    const int gt  = tid & 127;       // thread within group
    const int w4 = gt >> 5, lane = gt & 31;
    const int t = lane & 3, g = lane >> 2;
    const int t2 = t * 2;
    const int lr0 = 16 * w4 + g;     // local row (acc c0/c1), 0..63
    const int lr1 = lr0 + 8;
    const int b0 = blockIdx.x * TB;
    const int fbase = blockIdx.y * (2 * FG) + gid * FG;
    const int grow0 = b0 + lr0, grow1 = b0 + lr1;

    float* fs  = (float*)(smem + FS_OFF) + gid * GF;
    float* sx    = fs + SX_I;
    float* sw1   = fs + SW1_I;
    float* sb1   = fs + SB1_I;
    float* sbias = fs + SBIAS_I;
    float* swv   = fs + SWV_I;
    float* sc    = fs + SC_I;

    const uint32_t smem_u32 = (uint32_t)__cvta_generic_to_shared(smem);
    const uint32_t wgbase = smem_u32 + (uint32_t)gid * 98304u;   // 3 x 32KB ring
    const char* const wgen = smem + gid * 98304;

    const int t0 = a[grow0], t1 = a[grow1];
    const int t0w = t0 * H_SZ, t1w = t1 * H_SZ;

    float acc[16][4];
    uint32_t Ah[8][4];
    float bbs[16][4];
#pragma unroll
    for (int nt = 0; nt < 16; nt++)
#pragma unroll
        for (int j = 0; j < 4; j++) bbs[nt][j] = 0.0f;
    float yacc0 = 0.0f, yacc1 = 0.0f;

    // prologue: steps 0 and 1 into ring slots 0 and 1
    {
        const char* g0 = (const char*)&g_wp[0][fbase][0];
        const char* g1 = (const char*)&g_wp[1][fbase][0];
#pragma unroll
        for (int i = 0; i < 16; i++) {
            int b = (gt + i * GT) * 16;
            cp16(wgbase + b, g0 + b);
        }
        cp_commit();
#pragma unroll
        for (int i = 0; i < 16; i++) {
            int b = (gt + i * GT) * 16;
            cp16(wgbase + 32768u + b, g1 + b);
        }
        cp_commit();
    }

    for (int ff = 0; ff < FG; ff++) {
        const int f = fbase + ff;
        GBAR();   // prev feature consumers done with small buffers
        if (gt < TB) sx[gt] = x[(long)(b0 + gt) * F_SZ + f];
        sw1[gt]         = W1[f * H_SZ + gt];
        sb1[gt]         = b1[f * H_SZ + gt];
        sbias[gt]       = b2[f * H_SZ + gt];
        sbias[128 + gt] = b3[f * H_SZ + gt];
        sbias[256 + gt] = b4[f * H_SZ + gt];
        swv[gt]       = g_wv[f * 256 + gt];
        swv[128 + gt] = g_wv[f * 256 + 128 + gt];
        if (gt < 2) sc[gt] = g_c[f * 2 + gt];
        GBAR();

        // ---- layer 1: build fp16 A-fragments directly ----
        {
            const float xv0 = sx[lr0], xv1 = sx[lr1];
#pragma unroll
            for (int kk = 0; kk < 8; kk++) {
                const int cA = 16 * kk + t2, cB = cA + 8;
                float2 wA = *(const float2*)&sw1[cA];
                float2 bA = *(const float2*)&sb1[cA];
                float2 wB = *(const float2*)&sw1[cB];
                float2 bB = *(const float2*)&sb1[cB];
                Ah[kk][0] = pack2h(elu_f(xv0 * wA.x + bA.x),
                                   elu_f(xv0 * wA.y + bA.y));
                Ah[kk][1] = pack2h(elu_f(xv1 * wA.x + bA.x),
                                   elu_f(xv1 * wA.y + bA.y));
                Ah[kk][2] = pack2h(elu_f(xv0 * wB.x + bB.x),
                                   elu_f(xv0 * wB.y + bB.y));
                Ah[kk][3] = pack2h(elu_f(xv1 * wB.x + bB.x),
                                   elu_f(xv1 * wB.y + bB.y));
            }
        }

#pragma unroll 1
        for (int l = 0; l < 3; l++) {
            const int step = ff * 3 + l;
            if (step == NSTEP - 1) cp_wait0(); else cp_wait1();
            GBAR();   // ring slot step%3 ready & all warps past step-1 GEMM

            // prefetch step+2 into slot (step+2)%3 (last read at step-1)
            const int s2 = step + 2;
            if (s2 < NSTEP) {
                const char* nx = (const char*)&g_wp[s2 % 3][fbase + s2 / 3][0];
                const uint32_t dst = wgbase + (uint32_t)(s2 % 3) * 32768u;
#pragma unroll
                for (int i = 0; i < 16; i++) {
                    int b = (gt + i * GT) * 16;
                    cp16(dst + b, nx + b);
                }
                cp_commit();
            }

            const uint32_t* Wh =
                (const uint32_t*)(wgen + (step % 3) * 32768) + lane * 4;

            // ---- single-pass fp16 GEMM, LDS.128 feeds 2 HMMAs ----
#pragma unroll
            for (int nt = 0; nt < 16; nt++) {
                acc[nt][0] = 0.f; acc[nt][1] = 0.f;
                acc[nt][2] = 0.f; acc[nt][3] = 0.f;
            }
#pragma unroll
            for (int ks = 0; ks < 8; ks++) {
                const uint32_t* bp = Wh + ks * 1024;
#pragma unroll
                for (int ntp = 0; ntp < 8; ntp++) {
                    uint4 w = *(const uint4*)(bp + ntp * 128);
                    mma16816(acc[2 * ntp],     Ah[ks], w.x, w.y);
                    mma16816(acc[2 * ntp + 1], Ah[ks], w.z, w.w);
                }
            }

            if (l < 2) {
                // ---- epilogue: bias + ELU + fp16 pack -> next A frags ----
                const float* sb = sbias + l * 128;
#pragma unroll
                for (int kk = 0; kk < 8; kk++) {
                    const int nt0 = 2 * kk, nt1 = 2 * kk + 1;
                    float2 bA = *(const float2*)&sb[8 * nt0 + t2];
                    float2 bB = *(const float2*)&sb[8 * nt1 + t2];
                    Ah[kk][0] = pack2h(elu_f(acc[nt0][0] + bA.x),
                                       elu_f(acc[nt0][1] + bA.y));
                    Ah[kk][1] = pack2h(elu_f(acc[nt0][2] + bA.x),
                                       elu_f(acc[nt0][3] + bA.y));
                    Ah[kk][2] = pack2h(elu_f(acc[nt1][0] + bB.x),
                                       elu_f(acc[nt1][1] + bB.y));
                    Ah[kk][3] = pack2h(elu_f(acc[nt1][2] + bB.x),
                                       elu_f(acc[nt1][3] + bB.y));
                }
            } else {
                // ---- layer-4 epilogue: bb accumulate + collapsed head ----
                const float* sb4 = sbias + 256;
                float y0 = 0.0f, y1 = 0.0f;
#pragma unroll
                for (int nt = 0; nt < 16; nt++) {
                    float2 b4v = *(const float2*)&sb4[8 * nt + t2];
                    float bb0 = acc[nt][0] + b4v.x;
                    float bb1 = acc[nt][1] + b4v.y;
                    float bb2 = acc[nt][2] + b4v.x;
                    float bb3 = acc[nt][3] + b4v.y;
                    bbs[nt][0] += bb0; bbs[nt][1] += bb1;
                    bbs[nt][2] += bb2; bbs[nt][3] += bb3;
                    float2 wv0 = *(const float2*)&swv[t0w + 8 * nt + t2];
                    float2 wv1 = *(const float2*)&swv[t1w + 8 * nt + t2];
                    y0 += bb0 * wv0.x + bb1 * wv0.y;
                    y1 += bb2 * wv1.x + bb3 * wv1.y;
                }
                if (t == 0) { y0 += sc[t0]; y1 += sc[t1]; }
                yacc0 += y0; yacc1 += y1;
            }
        }
    }

    // ---- finale: atomics into output ----
#pragma unroll
    for (int nt = 0; nt < 16; nt++) {
        const int col = 8 * nt + t2;
        atomicAdd(&out[(long)grow0 * H_SZ + col],     bbs[nt][0]);
        atomicAdd(&out[(long)grow0 * H_SZ + col + 1], bbs[nt][1]);
        atomicAdd(&out[(long)grow1 * H_SZ + col],     bbs[nt][2]);
        atomicAdd(&out[(long)grow1 * H_SZ + col + 1], bbs[nt][3]);
    }
    yacc0 += __shfl_xor_sync(0xffffffffu, yacc0, 1);
    yacc0 += __shfl_xor_sync(0xffffffffu, yacc0, 2);
    yacc1 += __shfl_xor_sync(0xffffffffu, yacc1, 1);
    yacc1 += __shfl_xor_sync(0xffffffffu, yacc1, 2);
    if (t == 0) {
        atomicAdd(&out[B_SZ * H_SZ + grow0], yacc0);
        atomicAdd(&out[B_SZ * H_SZ + grow1], yacc1);
    }
}

// ---------------- launch ----------------
extern "C" void kernel_launch(void* const* d_in, const int* in_sizes, int n_in,
                              void* d_out, int out_size) {
    const float* x   = (const float*)d_in[0];
    const int*   a   = (const int*)d_in[1];
    const float* W1  = (const float*)d_in[2];
    const float* b1  = (const float*)d_in[3];
    const float* W2  = (const float*)d_in[4];
    const float* b2  = (const float*)d_in[5];
    const float* W3  = (const float*)d_in[6];
    const float* b3  = (const float*)d_in[7];
    const float* W4  = (const float*)d_in[8];
    const float* b4  = (const float*)d_in[9];
    const float* Wh1 = (const float*)d_in[10];
    const float* bh1 = (const float*)d_in[11];
    const float* Wh2 = (const float*)d_in[12];
    const float* bh2 = (const float*)d_in[13];
    float* out = (float*)d_out;

    cudaFuncSetAttribute(nam_main, cudaFuncAttributeMaxDynamicSharedMemorySize,
                         SMEM_BYTES);

    const int zero_blocks = (out_size + THREADS - 1) / THREADS;
    nam_setup<<<3 * F_SZ + F_SZ * T_SZ + zero_blocks, THREADS>>>(
        out, out_size, W2, W3, W4, Wh1, bh1, Wh2, bh2);

    dim3 grid(B_SZ / TB, F_SZ / (2 * FG));
    nam_main<<<grid, THREADS, SMEM_BYTES>>>(x, a, W1, b1, b2, b3, b4, out);
}